// round 4
// baseline (speedup 1.0000x reference)
#include <cuda_runtime.h>
#include <cstdint>
#include <math.h>

// ---------------------------------------------------------------- constants
#define D_IN    2048
#define HEADS   16
#define GROUPS  2
#define HD      128
#define BATCH   8
#define SEQ     512
#define CACHE   256
#define T_TOT   768
#define M_ROWS  (BATCH*SEQ)                 // 4096
#define QKV_N   2560
#define OUT_O_SIZE (M_ROWS*D_IN)
#define OUT_K_SIZE (BATCH*T_TOT*GROUPS*HD)

// ---------------------------------------------------------------- scratch
__device__ float g_qkv[M_ROWS * QKV_N];
__device__ float g_q[M_ROWS * D_IN];             // roped+scaled q, per bg: (r*512+s, 128)
__device__ float g_attn[M_ROWS * D_IN];
__device__ float g_scores[16 * 4096 * T_TOT];
__device__ float g_wT[QKV_N * D_IN];             // combined [n_qkv][2048]
__device__ float g_woT[D_IN * D_IN];             // [n][2048]
__device__ float g_vT[16 * HD * T_TOT];          // per bg: [hd][768]
__device__ float g_bias[QKV_N];

// ---------------------------------------------------------------- helpers
__device__ __forceinline__ uint32_t smem_u32(const void* p) {
    uint32_t a;
    asm("{ .reg .u64 t; cvta.to.shared.u64 t, %1; cvt.u32.u64 %0, t; }" : "=r"(a) : "l"(p));
    return a;
}
__device__ __forceinline__ uint32_t f2tf32(float f) {
    uint32_t r;
    asm("cvt.rna.tf32.f32 %0, %1;" : "=r"(r) : "f"(f));
    return r;
}
__device__ __forceinline__ void mma_tf32(float c[4],
                                         uint32_t a0, uint32_t a1, uint32_t a2, uint32_t a3,
                                         uint32_t b0, uint32_t b1) {
    asm volatile(
        "mma.sync.aligned.m16n8k8.row.col.f32.tf32.tf32.f32 "
        "{%0,%1,%2,%3}, {%4,%5,%6,%7}, {%8,%9}, {%0,%1,%2,%3};"
        : "+f"(c[0]), "+f"(c[1]), "+f"(c[2]), "+f"(c[3])
        : "r"(a0), "r"(a1), "r"(a2), "r"(a3), "r"(b0), "r"(b1));
}

#define CP_ASYNC16(dst, src) \
    asm volatile("cp.async.cg.shared.global [%0], [%1], 16;" :: "r"(dst), "l"(src) : "memory")
#define CP_COMMIT() asm volatile("cp.async.commit_group;" ::: "memory")
#define CP_WAIT1()  asm volatile("cp.async.wait_group 1;" ::: "memory")

// ---------------------------------------------------------------- GEMM core
// CTA tile 128x128, K chunk 32, 128 threads = 4 warps (2m x 2n), warp 64x64.
// 3-stage cp.async pipeline. smem stores raw fp32; cvt.rna at fragment load.
#define SROW 36
#define STAGE_FLOATS (2 * 128 * SROW)            // 9216
#define NSTAGE 3
#define GEMM_SMEM_BYTES (NSTAGE * STAGE_FLOATS * 4)  // 110592

__device__ __forceinline__ void mma_gemm(
    const float* __restrict__ A, int lda,
    const float* __restrict__ B, int ldb,
    int n_chunks, float* sm, float c[4][8][4])
{
    const int tid  = threadIdx.x;
    const int lane = tid & 31;
    const int wid  = tid >> 5;
    const int wm   = wid >> 1;
    const int wn   = wid & 1;
    const uint32_t sbase = smem_u32(sm);

    #pragma unroll
    for (int mt = 0; mt < 4; mt++)
        #pragma unroll
        for (int nt = 0; nt < 8; nt++)
            #pragma unroll
            for (int q = 0; q < 4; q++) c[mt][nt][q] = 0.f;

    auto issue = [&](int chunk, int stage) {
        if (chunk < n_chunks) {
            uint32_t sA = sbase + stage * (STAGE_FLOATS * 4);
            uint32_t sB = sA + 128 * SROW * 4;
            const float* ap = A + (size_t)tid * lda + chunk * 32;
            uint32_t da = sA + tid * (SROW * 4);
            #pragma unroll
            for (int q = 0; q < 8; q++) CP_ASYNC16(da + q * 16, ap + q * 4);
            const float* bp = B + (size_t)tid * ldb + chunk * 32;
            uint32_t db = sB + tid * (SROW * 4);
            #pragma unroll
            for (int q = 0; q < 8; q++) CP_ASYNC16(db + q * 16, bp + q * 4);
        }
        CP_COMMIT();
    };

    auto compute = [&](int s) {
        const float* As = sm + s * STAGE_FLOATS;
        const float* Bs = As + 128 * SROW;
        const float* ap = As + (wm * 64 + (lane >> 2)) * SROW + (lane & 3);
        const float* bp = Bs + (wn * 64 + (lane >> 2)) * SROW + (lane & 3);
        #pragma unroll
        for (int ks = 0; ks < 4; ks++) {
            uint32_t af[4][4];
            #pragma unroll
            for (int mt = 0; mt < 4; mt++) {
                const float* p = ap + mt * 16 * SROW + ks * 8;
                af[mt][0] = f2tf32(p[0]);
                af[mt][1] = f2tf32(p[8 * SROW]);
                af[mt][2] = f2tf32(p[4]);
                af[mt][3] = f2tf32(p[8 * SROW + 4]);
            }
            #pragma unroll
            for (int nt = 0; nt < 8; nt++) {
                const float* p = bp + nt * 8 * SROW + ks * 8;
                uint32_t b0 = f2tf32(p[0]), b1 = f2tf32(p[4]);
                #pragma unroll
                for (int mt = 0; mt < 4; mt++)
                    mma_tf32(c[mt][nt], af[mt][0], af[mt][1], af[mt][2], af[mt][3], b0, b1);
            }
        }
    };

    issue(0, 0);
    issue(1, 1);
    for (int i = 0; i < n_chunks; i++) {
        issue(i + 2, (i + 2) % NSTAGE);
        CP_WAIT1();
        __syncthreads();
        compute(i % NSTAGE);
        __syncthreads();
    }
}

// Epilogue coordinates within 128x128 tile (4 warps, 64x64 each)
#define EPI_ROW(mt, half) ((((threadIdx.x >> 5) >> 1) * 64) + (mt) * 16 + ((threadIdx.x & 31) >> 2) + (half) * 8)
#define EPI_COL(nt)       ((((threadIdx.x >> 5) & 1) * 64) + (nt) * 8 + ((threadIdx.x & 31) & 3) * 2)

// ---------------------------------------------------------------- kernels

// QKV projection: x(4096x2048) @ Wqkv^T(from g_wT) + g_bias -> g_qkv
__global__ void __launch_bounds__(128) qkv_gemm_kernel(const float* __restrict__ x)
{
    extern __shared__ float sm[];
    int row0 = blockIdx.x * 128;
    int n0 = blockIdx.y * 128;

    float c[4][8][4];
    mma_gemm(x + (size_t)row0 * D_IN, D_IN, g_wT + (size_t)n0 * D_IN, D_IN,
             D_IN / 32, sm, c);

    #pragma unroll
    for (int mt = 0; mt < 4; mt++)
        #pragma unroll
        for (int half = 0; half < 2; half++) {
            int r = row0 + EPI_ROW(mt, half);
            #pragma unroll
            for (int nt = 0; nt < 8; nt++) {
                int cl = EPI_COL(nt);
                float2 v;
                v.x = c[mt][nt][half*2+0] + g_bias[n0 + cl];
                v.y = c[mt][nt][half*2+1] + g_bias[n0 + cl + 1];
                *(float2*)&g_qkv[(size_t)r * QKV_N + n0 + cl] = v;
            }
        }
}

// Scores: per (b,g): g_q(4096x128) @ k_cache^T -> g_scores(4096x768)
__global__ void __launch_bounds__(128) scores_gemm_kernel(const float* __restrict__ kcache)
{
    extern __shared__ float sm[];
    int bg = blockIdx.z;
    int b = bg >> 1, g = bg & 1;
    int row0 = blockIdx.x * 128;
    int n0 = blockIdx.y * 128;

    const float* A = g_q + (size_t)bg * 4096 * HD + (size_t)row0 * HD;
    const float* B = kcache + ((size_t)b * T_TOT + n0) * (GROUPS * HD) + g * HD;

    float c[4][8][4];
    mma_gemm(A, HD, B, GROUPS * HD, HD / 32, sm, c);

    float* base = g_scores + (size_t)bg * 4096 * T_TOT;
    #pragma unroll
    for (int mt = 0; mt < 4; mt++)
        #pragma unroll
        for (int half = 0; half < 2; half++) {
            int r = row0 + EPI_ROW(mt, half);
            #pragma unroll
            for (int nt = 0; nt < 8; nt++) {
                int cl = EPI_COL(nt);
                float2 v = make_float2(c[mt][nt][half*2+0], c[mt][nt][half*2+1]);
                *(float2*)&base[(size_t)r * T_TOT + n0 + cl] = v;
            }
        }
}

// PV: per (b,g): probs(4096x768) @ V(768x128) via g_vT -> g_attn
__global__ void __launch_bounds__(128) pv_gemm_kernel()
{
    extern __shared__ float sm[];
    int bg = blockIdx.y;
    int b = bg >> 1, g = bg & 1;
    int row0 = blockIdx.x * 128;

    const float* A = g_scores + (size_t)bg * 4096 * T_TOT + (size_t)row0 * T_TOT;
    const float* B = g_vT + (size_t)bg * HD * T_TOT;   // [hd][768]

    float c[4][8][4];
    mma_gemm(A, T_TOT, B, T_TOT, T_TOT / 32, sm, c);

    #pragma unroll
    for (int mt = 0; mt < 4; mt++)
        #pragma unroll
        for (int half = 0; half < 2; half++) {
            int m = row0 + EPI_ROW(mt, half);
            int rh = m >> 9, s_ = m & 511;
            float* dst = g_attn + ((size_t)b * SEQ + s_) * D_IN + (g * 8 + rh) * HD;
            #pragma unroll
            for (int nt = 0; nt < 8; nt++) {
                int cl = EPI_COL(nt);
                float2 v = make_float2(c[mt][nt][half*2+0], c[mt][nt][half*2+1]);
                *(float2*)&dst[cl] = v;
            }
        }
}

// Output projection: g_attn(4096x2048) @ Wo(via g_woT) + bo -> out_o
__global__ void __launch_bounds__(128) outproj_gemm_kernel(
    const float* __restrict__ bo, float* __restrict__ out_o)
{
    extern __shared__ float sm[];
    int row0 = blockIdx.x * 128;
    int n0 = blockIdx.y * 128;

    float c[4][8][4];
    mma_gemm(g_attn + (size_t)row0 * D_IN, D_IN, g_woT + (size_t)n0 * D_IN, D_IN,
             D_IN / 32, sm, c);

    #pragma unroll
    for (int mt = 0; mt < 4; mt++)
        #pragma unroll
        for (int half = 0; half < 2; half++) {
            int r = row0 + EPI_ROW(mt, half);
            #pragma unroll
            for (int nt = 0; nt < 8; nt++) {
                int cl = EPI_COL(nt);
                float2 v;
                v.x = c[mt][nt][half*2+0] + bo[n0 + cl];
                v.y = c[mt][nt][half*2+1] + bo[n0 + cl + 1];
                *(float2*)&out_o[(size_t)r * D_IN + n0 + cl] = v;
            }
        }
}

// ---------------------------------------------------------------- transposes
// src [K][N] row-major -> dst [N][K] row-major
__global__ void transpose_kernel(const float* __restrict__ src, float* __restrict__ dst,
                                 int K, int N)
{
    __shared__ float t[32][33];
    int n0 = blockIdx.x * 32, k0 = blockIdx.y * 32;
    int tx = threadIdx.x, ty = threadIdx.y;   // 32 x 8
    #pragma unroll
    for (int j = 0; j < 32; j += 8)
        t[ty + j][tx] = src[(size_t)(k0 + ty + j) * N + n0 + tx];
    __syncthreads();
    #pragma unroll
    for (int j = 0; j < 32; j += 8)
        dst[(size_t)(n0 + ty + j) * K + k0 + tx] = t[tx][ty + j];
}

__global__ void bias_combine_kernel(const float* __restrict__ bq,
                                    const float* __restrict__ bk,
                                    const float* __restrict__ bv)
{
    int i = blockIdx.x * blockDim.x + threadIdx.x;
    if (i >= QKV_N) return;
    float v;
    if (i < 2048) v = bq[i];
    else if (i < 2304) v = bk[i - 2048];
    else v = bv[i - 2304];
    g_bias[i] = v;
}

// ---------------------------------------------------------------- elementwise

__global__ void softmax_kernel()
{
    int row = blockIdx.x * 8 + (threadIdx.x >> 5);
    int lane = threadIdx.x & 31;
    float* p = g_scores + (size_t)row * T_TOT;

    float v[24];
    #pragma unroll
    for (int j = 0; j < 6; j++) {
        float4 t = *(const float4*)(p + lane * 4 + j * 128);
        v[j*4+0] = t.x; v[j*4+1] = t.y; v[j*4+2] = t.z; v[j*4+3] = t.w;
    }
    float mx = -1e30f;
    #pragma unroll
    for (int j = 0; j < 24; j++) mx = fmaxf(mx, v[j]);
    #pragma unroll
    for (int off = 16; off >= 1; off >>= 1)
        mx = fmaxf(mx, __shfl_xor_sync(0xffffffffu, mx, off));
    float sum = 0.f;
    #pragma unroll
    for (int j = 0; j < 24; j++) { v[j] = __expf(v[j] - mx); sum += v[j]; }
    #pragma unroll
    for (int off = 16; off >= 1; off >>= 1)
        sum += __shfl_xor_sync(0xffffffffu, sum, off);
    float inv = 1.f / sum;
    #pragma unroll
    for (int j = 0; j < 6; j++) {
        float4 t = make_float4(v[j*4]*inv, v[j*4+1]*inv, v[j*4+2]*inv, v[j*4+3]*inv);
        *(float4*)(p + lane * 4 + j * 128) = t;
    }
}

__global__ void rope_q_kernel()
{
    int idx = blockIdx.x * blockDim.x + threadIdx.x;
    int j = idx & 63;
    int h = (idx >> 6) & 15;
    int m = idx >> 10;
    const float* src = g_qkv + (size_t)m * QKV_N + h * HD;
    float x1 = src[j], x2 = src[j + 64];
    int s = m & 511, b = m >> 9;
    float pos = (float)(CACHE + s);
    float freq = pos * expf(-(float)j * (9.210340371976184f / 64.f));
    float sn, cs; sincosf(freq, &sn, &cs);
    const float SCALE = 0.08838834764831845f;
    float* dst = g_q + (((size_t)b * HEADS + h) * SEQ + s) * HD;
    dst[j]      = (x1 * cs - x2 * sn) * SCALE;
    dst[j + 64] = (x2 * cs + x1 * sn) * SCALE;
}

__global__ void rope_kv_kernel(float* __restrict__ out_k, float* __restrict__ out_v)
{
    int idx = blockIdx.x * blockDim.x + threadIdx.x;
    int j = idx & 63;
    int g = (idx >> 6) & 1;
    int m = idx >> 7;
    const float* ksrc = g_qkv + (size_t)m * QKV_N + 2048 + g * HD;
    const float* vsrc = g_qkv + (size_t)m * QKV_N + 2304 + g * HD;
    float x1 = ksrc[j], x2 = ksrc[j + 64];
    int s = m & 511, b = m >> 9;
    float pos = (float)(CACHE + s);
    float freq = pos * expf(-(float)j * (9.210340371976184f / 64.f));
    float sn, cs; sincosf(freq, &sn, &cs);
    size_t base = (((size_t)b * T_TOT + CACHE + s) * GROUPS + g) * HD;
    out_k[base + j]      = x1 * cs - x2 * sn;
    out_k[base + j + 64] = x2 * cs + x1 * sn;
    out_v[base + j]      = vsrc[j];
    out_v[base + j + 64] = vsrc[j + 64];
}

__global__ void copy_prev_kernel(const float* __restrict__ prev_k,
                                 const float* __restrict__ prev_v,
                                 float* __restrict__ out_k,
                                 float* __restrict__ out_v)
{
    int idx = blockIdx.x * blockDim.x + threadIdx.x;
    if (idx >= BATCH * CACHE * GROUPS * HD) return;
    int b = idx >> 16;
    int r = idx & 65535;
    out_k[(size_t)b * (T_TOT * GROUPS * HD) + r] = prev_k[idx];
    out_v[(size_t)b * (T_TOT * GROUPS * HD) + r] = prev_v[idx];
}

// g_vT[bg][hd][t] for t in [0,256) from prev_v
__global__ void vt_prev_kernel(const float* __restrict__ prev_v)
{
    int idx = blockIdx.x * blockDim.x + threadIdx.x;   // 16*128*256
    int t = idx & 255;
    int hd = (idx >> 8) & 127;
    int bg = idx >> 15;
    int b = bg >> 1, g = bg & 1;
    g_vT[(size_t)bg * HD * T_TOT + (size_t)hd * T_TOT + t] =
        prev_v[(((size_t)b * CACHE + t) * GROUPS + g) * HD + hd];
}

// g_vT[bg][hd][256+s] for s in [0,512) from g_qkv v-section
__global__ void vt_new_kernel()
{
    int idx = blockIdx.x * blockDim.x + threadIdx.x;   // 16*128*512
    int s = idx & 511;
    int hd = (idx >> 9) & 127;
    int bg = idx >> 16;
    int b = bg >> 1, g = bg & 1;
    g_vT[(size_t)bg * HD * T_TOT + (size_t)hd * T_TOT + CACHE + s] =
        g_qkv[((size_t)b * SEQ + s) * QKV_N + 2304 + g * HD + hd];
}

// ---------------------------------------------------------------- launcher
extern "C" void kernel_launch(void* const* d_in, const int* in_sizes, int n_in,
                              void* d_out, int out_size)
{
    const float* x      = (const float*)d_in[0];
    const float* prev_k = (const float*)d_in[1];
    const float* prev_v = (const float*)d_in[2];
    const float* Wq     = (const float*)d_in[3];
    const float* bq     = (const float*)d_in[4];
    const float* Wk     = (const float*)d_in[5];
    const float* bk     = (const float*)d_in[6];
    const float* Wv     = (const float*)d_in[7];
    const float* bv     = (const float*)d_in[8];
    const float* Wo     = (const float*)d_in[9];
    const float* bo     = (const float*)d_in[10];

    float* out_o = (float*)d_out;
    float* out_k = out_o + OUT_O_SIZE;
    float* out_v = out_k + OUT_K_SIZE;

    static bool attr_set = false;
    if (!attr_set) {
        cudaFuncSetAttribute(qkv_gemm_kernel,     cudaFuncAttributeMaxDynamicSharedMemorySize, GEMM_SMEM_BYTES);
        cudaFuncSetAttribute(scores_gemm_kernel,  cudaFuncAttributeMaxDynamicSharedMemorySize, GEMM_SMEM_BYTES);
        cudaFuncSetAttribute(pv_gemm_kernel,      cudaFuncAttributeMaxDynamicSharedMemorySize, GEMM_SMEM_BYTES);
        cudaFuncSetAttribute(outproj_gemm_kernel, cudaFuncAttributeMaxDynamicSharedMemorySize, GEMM_SMEM_BYTES);
        attr_set = true;
    }

    // 0. Weight transposes + bias combine (K-contiguous B operands)
    {
        float* wT = nullptr; cudaGetSymbolAddress((void**)&wT, g_wT);
        float* woT = nullptr; cudaGetSymbolAddress((void**)&woT, g_woT);
        dim3 blk(32, 8);
        transpose_kernel<<<dim3(64, 64), blk>>>(Wq, wT, D_IN, D_IN);
        transpose_kernel<<<dim3(8, 64), blk>>>(Wk, wT + 2048 * D_IN, D_IN, 256);
        transpose_kernel<<<dim3(8, 64), blk>>>(Wv, wT + 2304 * D_IN, D_IN, 256);
        transpose_kernel<<<dim3(64, 64), blk>>>(Wo, woT, D_IN, D_IN);
        bias_combine_kernel<<<(QKV_N + 255) / 256, 256>>>(bq, bk, bv);
    }

    // 1. kv-cache history (+ transposed V history)
    copy_prev_kernel<<<2048, 256>>>(prev_k, prev_v, out_k, out_v);
    vt_prev_kernel<<<(16 * 128 * 256) / 256, 256>>>(prev_v);

    // 2. QKV projection
    qkv_gemm_kernel<<<dim3(M_ROWS / 128, QKV_N / 128), 128, GEMM_SMEM_BYTES>>>(x);

    // 3. RoPE q / RoPE k + v copy / transposed V
    rope_q_kernel<<<M_ROWS * HEADS * 64 / 256, 256>>>();
    rope_kv_kernel<<<M_ROWS * GROUPS * 64 / 256, 256>>>(out_k, out_v);
    vt_new_kernel<<<(16 * 128 * 512) / 256, 256>>>();

    // 4. Scores GEMM
    scores_gemm_kernel<<<dim3(32, T_TOT / 128, 16), 128, GEMM_SMEM_BYTES>>>(out_k);

    // 5. Softmax
    softmax_kernel<<<(16 * 4096) / 8, 256>>>();

    // 6. PV GEMM
    pv_gemm_kernel<<<dim3(32, 16), 128, GEMM_SMEM_BYTES>>>();

    // 7. Output projection
    outproj_gemm_kernel<<<dim3(M_ROWS / 128, D_IN / 128), 128, GEMM_SMEM_BYTES>>>(bo, out_o);
}

// round 5
// speedup vs baseline: 1.5734x; 1.5734x over previous
#include <cuda_runtime.h>
#include <cstdint>
#include <math.h>

// ---------------------------------------------------------------- constants
#define D_IN    2048
#define HEADS   16
#define GROUPS  2
#define HD      128
#define BATCH   8
#define SEQ     512
#define CACHE   256
#define T_TOT   768
#define M_ROWS  (BATCH*SEQ)                 // 4096
#define QKV_N   2560
#define OUT_O_SIZE (M_ROWS*D_IN)
#define OUT_K_SIZE (BATCH*T_TOT*GROUPS*HD)

// ---------------------------------------------------------------- scratch
__device__ float g_qkv[M_ROWS * QKV_N];
__device__ float g_q[M_ROWS * D_IN];             // roped+scaled q, per bg
__device__ float g_attn[M_ROWS * D_IN];
__device__ float g_scores[16 * 4096 * T_TOT];
__device__ float g_wT[QKV_N * D_IN];             // combined [n_qkv][2048]
__device__ float g_woT[D_IN * D_IN];             // [n][2048]
__device__ float g_vT[16 * HD * T_TOT];          // per bg: [hd][768]
__device__ float g_bias[QKV_N];

// ---------------------------------------------------------------- helpers
__device__ __forceinline__ uint32_t smem_u32(const void* p) {
    uint32_t a;
    asm("{ .reg .u64 t; cvta.to.shared.u64 t, %1; cvt.u32.u64 %0, t; }" : "=r"(a) : "l"(p));
    return a;
}
__device__ __forceinline__ uint32_t f2tf32(float f) {
    uint32_t r;
    asm("cvt.rna.tf32.f32 %0, %1;" : "=r"(r) : "f"(f));
    return r;
}
__device__ __forceinline__ void mma_tf32(float c[4],
                                         uint32_t a0, uint32_t a1, uint32_t a2, uint32_t a3,
                                         uint32_t b0, uint32_t b1) {
    asm volatile(
        "mma.sync.aligned.m16n8k8.row.col.f32.tf32.tf32.f32 "
        "{%0,%1,%2,%3}, {%4,%5,%6,%7}, {%8,%9}, {%0,%1,%2,%3};"
        : "+f"(c[0]), "+f"(c[1]), "+f"(c[2]), "+f"(c[3])
        : "r"(a0), "r"(a1), "r"(a2), "r"(a3), "r"(b0), "r"(b1));
}

#define CP_ASYNC16(dst, src) \
    asm volatile("cp.async.cg.shared.global [%0], [%1], 16;" :: "r"(dst), "l"(src) : "memory")
#define CP_COMMIT() asm volatile("cp.async.commit_group;" ::: "memory")
#define CP_WAIT2()  asm volatile("cp.async.wait_group 2;" ::: "memory")

// ---------------------------------------------------------------- GEMM core
// CTA tile 128x128, K chunk 32, 256 threads = 8 warps (4m x 2n), warp 32x64.
// 3-stage cp.async pipeline; smem raw fp32; cvt.rna at fragment load.
#define SROW 36
#define STAGE_FLOATS (2 * 128 * SROW)            // 9216
#define NSTAGE 3
#define GEMM_SMEM_BYTES (NSTAGE * STAGE_FLOATS * 4)  // 110592

__device__ __forceinline__ void mma_gemm(
    const float* __restrict__ A, int lda,
    const float* __restrict__ B, int ldb,
    int n_chunks, float* sm, float c[2][8][4])
{
    const int tid  = threadIdx.x;
    const int lane = tid & 31;
    const int wid  = tid >> 5;
    const int wm   = wid >> 1;      // 0..3
    const int wn   = wid & 1;       // 0..1
    const uint32_t sbase = smem_u32(sm);

    // staging: 128 rows x 32 floats = 1024 x 16B per operand; 256 threads x 4
    const int srow0 = tid >> 3;          // base row (advance by 32)
    const int sc16  = (tid & 7);         // 16B column 0..7

    #pragma unroll
    for (int mt = 0; mt < 2; mt++)
        #pragma unroll
        for (int nt = 0; nt < 8; nt++)
            #pragma unroll
            for (int q = 0; q < 4; q++) c[mt][nt][q] = 0.f;

    auto issue = [&](int chunk, int stage) {
        if (chunk < n_chunks) {
            uint32_t sA = sbase + stage * (STAGE_FLOATS * 4);
            uint32_t sB = sA + 128 * SROW * 4;
            #pragma unroll
            for (int it = 0; it < 4; it++) {
                int row = srow0 + it * 32;
                const float* ap = A + (size_t)row * lda + chunk * 32 + sc16 * 4;
                CP_ASYNC16(sA + row * (SROW * 4) + sc16 * 16, ap);
                const float* bp = B + (size_t)row * ldb + chunk * 32 + sc16 * 4;
                CP_ASYNC16(sB + row * (SROW * 4) + sc16 * 16, bp);
            }
        }
        CP_COMMIT();
    };

    auto compute = [&](int s) {
        const float* As = sm + s * STAGE_FLOATS;
        const float* Bs = As + 128 * SROW;
        const float* ap = As + (wm * 32 + (lane >> 2)) * SROW + (lane & 3);
        const float* bp = Bs + (wn * 64 + (lane >> 2)) * SROW + (lane & 3);
        #pragma unroll
        for (int ks = 0; ks < 4; ks++) {
            uint32_t af[2][4];
            #pragma unroll
            for (int mt = 0; mt < 2; mt++) {
                const float* p = ap + mt * 16 * SROW + ks * 8;
                af[mt][0] = f2tf32(p[0]);
                af[mt][1] = f2tf32(p[8 * SROW]);
                af[mt][2] = f2tf32(p[4]);
                af[mt][3] = f2tf32(p[8 * SROW + 4]);
            }
            #pragma unroll
            for (int nt = 0; nt < 8; nt++) {
                const float* p = bp + nt * 8 * SROW + ks * 8;
                uint32_t b0 = f2tf32(p[0]), b1 = f2tf32(p[4]);
                #pragma unroll
                for (int mt = 0; mt < 2; mt++)
                    mma_tf32(c[mt][nt], af[mt][0], af[mt][1], af[mt][2], af[mt][3], b0, b1);
            }
        }
    };

    issue(0, 0);
    issue(1, 1);
    for (int i = 0; i < n_chunks; i++) {
        issue(i + 2, (i + 2) % NSTAGE);
        CP_WAIT2();
        __syncthreads();
        compute(i % NSTAGE);
        __syncthreads();
    }
}

// Epilogue coordinates within 128x128 tile (8 warps: 4m x 2n, warp 32x64)
#define EPI_ROW(mt, half)  (( (threadIdx.x >> 6) & 3 ) * 32 + (mt) * 16 + ((threadIdx.x & 31) >> 2) + (half) * 8)
#define EPI_COL(nt)        (( (threadIdx.x >> 5) & 1 ) * 64 + (nt) * 8 + ((threadIdx.x & 31) & 3) * 2)

// ---------------------------------------------------------------- kernels

__global__ void __launch_bounds__(256, 2) qkv_gemm_kernel(const float* __restrict__ x)
{
    extern __shared__ float sm[];
    int row0 = blockIdx.x * 128;
    int n0 = blockIdx.y * 128;

    float c[2][8][4];
    mma_gemm(x + (size_t)row0 * D_IN, D_IN, g_wT + (size_t)n0 * D_IN, D_IN,
             D_IN / 32, sm, c);

    #pragma unroll
    for (int mt = 0; mt < 2; mt++)
        #pragma unroll
        for (int half = 0; half < 2; half++) {
            int r = row0 + EPI_ROW(mt, half);
            #pragma unroll
            for (int nt = 0; nt < 8; nt++) {
                int cl = EPI_COL(nt);
                float2 v;
                v.x = c[mt][nt][half*2+0] + g_bias[n0 + cl];
                v.y = c[mt][nt][half*2+1] + g_bias[n0 + cl + 1];
                *(float2*)&g_qkv[(size_t)r * QKV_N + n0 + cl] = v;
            }
        }
}

__global__ void __launch_bounds__(256, 2) scores_gemm_kernel(const float* __restrict__ kcache)
{
    extern __shared__ float sm[];
    int bg = blockIdx.z;
    int b = bg >> 1, g = bg & 1;
    int row0 = blockIdx.x * 128;
    int n0 = blockIdx.y * 128;

    const float* A = g_q + (size_t)bg * 4096 * HD + (size_t)row0 * HD;
    const float* B = kcache + ((size_t)b * T_TOT + n0) * (GROUPS * HD) + g * HD;

    float c[2][8][4];
    mma_gemm(A, HD, B, GROUPS * HD, HD / 32, sm, c);

    float* base = g_scores + (size_t)bg * 4096 * T_TOT;
    #pragma unroll
    for (int mt = 0; mt < 2; mt++)
        #pragma unroll
        for (int half = 0; half < 2; half++) {
            int r = row0 + EPI_ROW(mt, half);
            #pragma unroll
            for (int nt = 0; nt < 8; nt++) {
                int cl = EPI_COL(nt);
                float2 v = make_float2(c[mt][nt][half*2+0], c[mt][nt][half*2+1]);
                *(float2*)&base[(size_t)r * T_TOT + n0 + cl] = v;
            }
        }
}

__global__ void __launch_bounds__(256, 2) pv_gemm_kernel()
{
    extern __shared__ float sm[];
    int bg = blockIdx.y;
    int b = bg >> 1, g = bg & 1;
    int row0 = blockIdx.x * 128;

    const float* A = g_scores + (size_t)bg * 4096 * T_TOT + (size_t)row0 * T_TOT;
    const float* B = g_vT + (size_t)bg * HD * T_TOT;   // [hd][768]

    float c[2][8][4];
    mma_gemm(A, T_TOT, B, T_TOT, T_TOT / 32, sm, c);

    #pragma unroll
    for (int mt = 0; mt < 2; mt++)
        #pragma unroll
        for (int half = 0; half < 2; half++) {
            int m = row0 + EPI_ROW(mt, half);
            int rh = m >> 9, s_ = m & 511;
            float* dst = g_attn + ((size_t)b * SEQ + s_) * D_IN + (g * 8 + rh) * HD;
            #pragma unroll
            for (int nt = 0; nt < 8; nt++) {
                int cl = EPI_COL(nt);
                float2 v = make_float2(c[mt][nt][half*2+0], c[mt][nt][half*2+1]);
                *(float2*)&dst[cl] = v;
            }
        }
}

__global__ void __launch_bounds__(256, 2) outproj_gemm_kernel(
    const float* __restrict__ bo, float* __restrict__ out_o)
{
    extern __shared__ float sm[];
    int row0 = blockIdx.x * 128;
    int n0 = blockIdx.y * 128;

    float c[2][8][4];
    mma_gemm(g_attn + (size_t)row0 * D_IN, D_IN, g_woT + (size_t)n0 * D_IN, D_IN,
             D_IN / 32, sm, c);

    #pragma unroll
    for (int mt = 0; mt < 2; mt++)
        #pragma unroll
        for (int half = 0; half < 2; half++) {
            int r = row0 + EPI_ROW(mt, half);
            #pragma unroll
            for (int nt = 0; nt < 8; nt++) {
                int cl = EPI_COL(nt);
                float2 v;
                v.x = c[mt][nt][half*2+0] + bo[n0 + cl];
                v.y = c[mt][nt][half*2+1] + bo[n0 + cl + 1];
                *(float2*)&out_o[(size_t)r * D_IN + n0 + cl] = v;
            }
        }
}

// ---------------------------------------------------------------- transposes
__global__ void transpose_kernel(const float* __restrict__ src, float* __restrict__ dst,
                                 int K, int N)
{
    __shared__ float t[32][33];
    int n0 = blockIdx.x * 32, k0 = blockIdx.y * 32;
    int tx = threadIdx.x, ty = threadIdx.y;   // 32 x 8
    #pragma unroll
    for (int j = 0; j < 32; j += 8)
        t[ty + j][tx] = src[(size_t)(k0 + ty + j) * N + n0 + tx];
    __syncthreads();
    #pragma unroll
    for (int j = 0; j < 32; j += 8)
        dst[(size_t)(n0 + ty + j) * K + k0 + tx] = t[tx][ty + j];
}

__global__ void bias_combine_kernel(const float* __restrict__ bq,
                                    const float* __restrict__ bk,
                                    const float* __restrict__ bv)
{
    int i = blockIdx.x * blockDim.x + threadIdx.x;
    if (i >= QKV_N) return;
    float v;
    if (i < 2048) v = bq[i];
    else if (i < 2304) v = bk[i - 2048];
    else v = bv[i - 2304];
    g_bias[i] = v;
}

// ---------------------------------------------------------------- elementwise

__global__ void __launch_bounds__(256) softmax_kernel()
{
    int row = blockIdx.x * 8 + (threadIdx.x >> 5);
    int lane = threadIdx.x & 31;
    float* p = g_scores + (size_t)row * T_TOT;

    float v[24];
    #pragma unroll
    for (int j = 0; j < 6; j++) {
        float4 t = *(const float4*)(p + lane * 4 + j * 128);
        v[j*4+0] = t.x; v[j*4+1] = t.y; v[j*4+2] = t.z; v[j*4+3] = t.w;
    }
    float mx = -1e30f;
    #pragma unroll
    for (int j = 0; j < 24; j++) mx = fmaxf(mx, v[j]);
    #pragma unroll
    for (int off = 16; off >= 1; off >>= 1)
        mx = fmaxf(mx, __shfl_xor_sync(0xffffffffu, mx, off));
    float sum = 0.f;
    #pragma unroll
    for (int j = 0; j < 24; j++) { v[j] = __expf(v[j] - mx); sum += v[j]; }
    #pragma unroll
    for (int off = 16; off >= 1; off >>= 1)
        sum += __shfl_xor_sync(0xffffffffu, sum, off);
    float inv = 1.f / sum;
    #pragma unroll
    for (int j = 0; j < 6; j++) {
        float4 t = make_float4(v[j*4]*inv, v[j*4+1]*inv, v[j*4+2]*inv, v[j*4+3]*inv);
        *(float4*)(p + lane * 4 + j * 128) = t;
    }
}

__global__ void rope_q_kernel()
{
    int idx = blockIdx.x * blockDim.x + threadIdx.x;
    int j = idx & 63;
    int h = (idx >> 6) & 15;
    int m = idx >> 10;
    const float* src = g_qkv + (size_t)m * QKV_N + h * HD;
    float x1 = src[j], x2 = src[j + 64];
    int s = m & 511, b = m >> 9;
    float pos = (float)(CACHE + s);
    float freq = pos * expf(-(float)j * (9.210340371976184f / 64.f));
    float sn, cs; sincosf(freq, &sn, &cs);
    const float SCALE = 0.08838834764831845f;
    float* dst = g_q + (((size_t)b * HEADS + h) * SEQ + s) * HD;
    dst[j]      = (x1 * cs - x2 * sn) * SCALE;
    dst[j + 64] = (x2 * cs + x1 * sn) * SCALE;
}

__global__ void rope_kv_kernel(float* __restrict__ out_k, float* __restrict__ out_v)
{
    int idx = blockIdx.x * blockDim.x + threadIdx.x;
    int j = idx & 63;
    int g = (idx >> 6) & 1;
    int m = idx >> 7;
    const float* ksrc = g_qkv + (size_t)m * QKV_N + 2048 + g * HD;
    const float* vsrc = g_qkv + (size_t)m * QKV_N + 2304 + g * HD;
    float x1 = ksrc[j], x2 = ksrc[j + 64];
    int s = m & 511, b = m >> 9;
    float pos = (float)(CACHE + s);
    float freq = pos * expf(-(float)j * (9.210340371976184f / 64.f));
    float sn, cs; sincosf(freq, &sn, &cs);
    size_t base = (((size_t)b * T_TOT + CACHE + s) * GROUPS + g) * HD;
    out_k[base + j]      = x1 * cs - x2 * sn;
    out_k[base + j + 64] = x2 * cs + x1 * sn;
    out_v[base + j]      = vsrc[j];
    out_v[base + j + 64] = vsrc[j + 64];
}

__global__ void copy_prev_kernel(const float* __restrict__ prev_k,
                                 const float* __restrict__ prev_v,
                                 float* __restrict__ out_k,
                                 float* __restrict__ out_v)
{
    int idx = blockIdx.x * blockDim.x + threadIdx.x;
    if (idx >= BATCH * CACHE * GROUPS * HD) return;
    int b = idx >> 16;
    int r = idx & 65535;
    out_k[(size_t)b * (T_TOT * GROUPS * HD) + r] = prev_k[idx];
    out_v[(size_t)b * (T_TOT * GROUPS * HD) + r] = prev_v[idx];
}

__global__ void vt_prev_kernel(const float* __restrict__ prev_v)
{
    int idx = blockIdx.x * blockDim.x + threadIdx.x;   // 16*128*256
    int t = idx & 255;
    int hd = (idx >> 8) & 127;
    int bg = idx >> 15;
    int b = bg >> 1, g = bg & 1;
    g_vT[(size_t)bg * HD * T_TOT + (size_t)hd * T_TOT + t] =
        prev_v[(((size_t)b * CACHE + t) * GROUPS + g) * HD + hd];
}

__global__ void vt_new_kernel()
{
    int idx = blockIdx.x * blockDim.x + threadIdx.x;   // 16*128*512
    int s = idx & 511;
    int hd = (idx >> 9) & 127;
    int bg = idx >> 16;
    int b = bg >> 1, g = bg & 1;
    g_vT[(size_t)bg * HD * T_TOT + (size_t)hd * T_TOT + CACHE + s] =
        g_qkv[((size_t)b * SEQ + s) * QKV_N + 2304 + g * HD + hd];
}

// ---------------------------------------------------------------- launcher
extern "C" void kernel_launch(void* const* d_in, const int* in_sizes, int n_in,
                              void* d_out, int out_size)
{
    const float* x      = (const float*)d_in[0];
    const float* prev_k = (const float*)d_in[1];
    const float* prev_v = (const float*)d_in[2];
    const float* Wq     = (const float*)d_in[3];
    const float* bq     = (const float*)d_in[4];
    const float* Wk     = (const float*)d_in[5];
    const float* bk     = (const float*)d_in[6];
    const float* Wv     = (const float*)d_in[7];
    const float* bv     = (const float*)d_in[8];
    const float* Wo     = (const float*)d_in[9];
    const float* bo     = (const float*)d_in[10];

    float* out_o = (float*)d_out;
    float* out_k = out_o + OUT_O_SIZE;
    float* out_v = out_k + OUT_K_SIZE;

    static bool attr_set = false;
    if (!attr_set) {
        cudaFuncSetAttribute(qkv_gemm_kernel,     cudaFuncAttributeMaxDynamicSharedMemorySize, GEMM_SMEM_BYTES);
        cudaFuncSetAttribute(scores_gemm_kernel,  cudaFuncAttributeMaxDynamicSharedMemorySize, GEMM_SMEM_BYTES);
        cudaFuncSetAttribute(pv_gemm_kernel,      cudaFuncAttributeMaxDynamicSharedMemorySize, GEMM_SMEM_BYTES);
        cudaFuncSetAttribute(outproj_gemm_kernel, cudaFuncAttributeMaxDynamicSharedMemorySize, GEMM_SMEM_BYTES);
        attr_set = true;
    }

    // 0. Weight transposes + bias combine
    {
        float* wT = nullptr; cudaGetSymbolAddress((void**)&wT, g_wT);
        float* woT = nullptr; cudaGetSymbolAddress((void**)&woT, g_woT);
        dim3 blk(32, 8);
        transpose_kernel<<<dim3(64, 64), blk>>>(Wq, wT, D_IN, D_IN);
        transpose_kernel<<<dim3(8, 64), blk>>>(Wk, wT + 2048 * D_IN, D_IN, 256);
        transpose_kernel<<<dim3(8, 64), blk>>>(Wv, wT + 2304 * D_IN, D_IN, 256);
        transpose_kernel<<<dim3(64, 64), blk>>>(Wo, woT, D_IN, D_IN);
        bias_combine_kernel<<<(QKV_N + 255) / 256, 256>>>(bq, bk, bv);
    }

    // 1. kv-cache history (+ transposed V history)
    copy_prev_kernel<<<2048, 256>>>(prev_k, prev_v, out_k, out_v);
    vt_prev_kernel<<<(16 * 128 * 256) / 256, 256>>>(prev_v);

    // 2. QKV projection
    qkv_gemm_kernel<<<dim3(M_ROWS / 128, QKV_N / 128), 256, GEMM_SMEM_BYTES>>>(x);

    // 3. RoPE q / RoPE k + v copy / transposed V
    rope_q_kernel<<<M_ROWS * HEADS * 64 / 256, 256>>>();
    rope_kv_kernel<<<M_ROWS * GROUPS * 64 / 256, 256>>>(out_k, out_v);
    vt_new_kernel<<<(16 * 128 * 512) / 256, 256>>>();

    // 4. Scores GEMM
    scores_gemm_kernel<<<dim3(32, T_TOT / 128, 16), 256, GEMM_SMEM_BYTES>>>(out_k);

    // 5. Softmax
    softmax_kernel<<<(16 * 4096) / 8, 256>>>();

    // 6. PV GEMM
    pv_gemm_kernel<<<dim3(32, 16), 256, GEMM_SMEM_BYTES>>>();

    // 7. Output projection
    outproj_gemm_kernel<<<dim3(M_ROWS / 128, D_IN / 128), 256, GEMM_SMEM_BYTES>>>(bo, out_o);
}